// round 12
// baseline (speedup 1.0000x reference)
#include <cuda_runtime.h>
#include <math.h>
#include <math_constants.h>

#define NTH  128     // Gauss-Legendre nodes in theta (matches reference)
#define NPH  256     // phi grid (matches reference)
#define MAXB 8192

// Scratch / tables in __device__ globals (no allocation allowed).
__device__ float4 g_nodes[NTH];      // {u, s=sqrt(1-u^2), s2=1-u^2, w}
__device__ float2 g_phi[NPH];        // {cos(phi_j), sin(phi_j)}
__device__ float  g_scal[MAXB * 8];  // per-batch: A2,Bc2,Bs2,bb2,bE2,M02,M0,base

// ---------------------------------------------------------------------------
// Init: compute 128-point Gauss-Legendre nodes/weights (fp64 Newton), and the
// phi cos/sin table. One block, 256 threads. Fixed 5 Newton iterations
// (deterministic; converges to ~1e-15 from the classical cosine guess).
// Recurrence restructured so the serial critical path is one DFMA per step:
//   p_j = fma(c1[j]*x, p_{j-1}, -(c2[j]*p_{j-2}))
// with c1,c2 precomputed in shared (one DDIV each, fully parallel).
// ---------------------------------------------------------------------------
__global__ void fb8_init_kernel() {
    __shared__ double c1s[NTH + 1];
    __shared__ double c2s[NTH + 1];
    int t = threadIdx.x;
    if (t >= 2 && t <= NTH) {
        c1s[t] = (2.0 * (double)t - 1.0) / (double)t;
        c2s[t] = ((double)t - 1.0) / (double)t;
    }
    __syncthreads();

    if (t < NTH) {
        const double n = (double)NTH;
        double x = cos(CUDART_PI * ((double)t + 0.75) / (n + 0.5));
        double p1 = x, p0 = 1.0, dp = 1.0;
        #pragma unroll 1
        for (int it = 0; it < 5; ++it) {
            p0 = 1.0;
            p1 = x;
            #pragma unroll 1
            for (int j = 2; j <= NTH; ++j) {
                double p2 = fma(c1s[j] * x, p1, -(c2s[j] * p0));
                p0 = p1;
                p1 = p2;
            }
            dp = n * (x * p1 - p0) / (x * x - 1.0);
            x -= p1 / dp;
        }
        double s2 = 1.0 - x * x;
        double w  = 2.0 / (s2 * dp * dp);
        g_nodes[t] = make_float4((float)x, (float)sqrt(s2), (float)s2, (float)w);
    }

    if (t < NPH) {
        double a = (double)t * (2.0 * CUDART_PI / (double)NPH);
        g_phi[t] = make_float2((float)cos(a), (float)sin(a));
    }
}

// ---------------------------------------------------------------------------
// Prep: per-batch geometry. Gamma = H(theta,phi) @ K(psi); project x onto the
// three Gamma columns; nu from (alpha,rho); fold everything into the few
// scalars the quadrature kernel needs (pre-scaled by log2(e) where useful).
// ---------------------------------------------------------------------------
__global__ void fb8_prep_kernel(
    const float* __restrict__ x,
    const float* __restrict__ theta, const float* __restrict__ phi,
    const float* __restrict__ psi,   const float* __restrict__ kappa,
    const float* __restrict__ beta,  const float* __restrict__ eta,
    const float* __restrict__ alpha, const float* __restrict__ rho,
    int B)
{
    int b = blockIdx.x * blockDim.x + threadIdx.x;
    if (b >= B) return;

    float x0 = x[3 * b + 0], x1 = x[3 * b + 1], x2 = x[3 * b + 2];
    float st, ct, sp, cp, sq, cq, sa, ca, sr, cr;
    sincosf(theta[b], &st, &ct);
    sincosf(phi[b],   &sp, &cp);
    sincosf(psi[b],   &sq, &cq);
    sincosf(alpha[b], &sa, &ca);
    sincosf(rho[b],   &sr, &cr);

    // Gamma columns (H @ K):
    // col0 = (ct, st*cp, st*sp)
    // col1 = (-st*cq, ct*cp*cq - sp*sq, ct*sp*cq + cp*sq)
    // col2 = ( st*sq, -ct*cp*sq - sp*cq, cp*cq - ct*sp*sq)
    float g1 = x0 * ct        + x1 * (st * cp)             + x2 * (st * sp);
    float g2 = x0 * (-st * cq) + x1 * (ct * cp * cq - sp * sq)
                               + x2 * (ct * sp * cq + cp * sq);
    float g3 = x0 * (st * sq) + x1 * (-ct * cp * sq - sp * cq)
                               + x2 * (cp * cq - ct * sp * sq);

    float nu0 = ca, nu1 = sa * cr, nu2 = sa * sr;
    float ngx = nu0 * g1 + nu1 * g2 + nu2 * g3;

    float kap = kappa[b], bet = beta[b], et = eta[b];
    float A  = kap * nu0;
    float Bc = kap * nu1;
    float Bs = kap * nu2;
    float bb = bet;
    float bE = bet * et;

    // Upper bound on expo over the sphere (stabilizer for logsumexp — any
    // finite shift is mathematically exact; this keeps exp args in range).
    float M0 = fabsf(A) + sqrtf(Bc * Bc + Bs * Bs)
             + fmaxf(0.0f, fmaxf(bb, -bE));

    float base = kap * ngx + bet * (g2 * g2 - et * g3 * g3);

    const float L2E = 1.4426950408889634074f;
    float* s = g_scal + (size_t)b * 8;
    s[0] = A  * L2E;
    s[1] = Bc * L2E;
    s[2] = Bs * L2E;
    s[3] = bb * L2E;
    s[4] = bE * L2E;
    s[5] = M0 * L2E;
    s[6] = M0;
    s[7] = base;
}

// ---------------------------------------------------------------------------
// Main: one block per batch element, one thread per phi column. Each thread
// sweeps the 128 theta nodes: expo(log2) = A2*u + C12*s + C22*s2 - M02,
// sum += w * exp2(expo). Single pass (analytic M0 bound), 4 accumulators,
// block logsumexp reduction, out[b] = logC - base.
// ---------------------------------------------------------------------------
__global__ __launch_bounds__(NPH)
void fb8_main_kernel(float* __restrict__ out)
{
    __shared__ float4 nd[NTH];
    __shared__ float  red[NPH / 32];

    const int b   = blockIdx.x;
    const int tid = threadIdx.x;

    if (tid < NTH) nd[tid] = g_nodes[tid];

    const float* s = g_scal + (size_t)b * 8;
    const float A2   = s[0];
    const float Bc2  = s[1];
    const float Bs2  = s[2];
    const float bb2  = s[3];
    const float bE2  = s[4];
    const float nM02 = -s[5];

    const float2 cs = g_phi[tid];
    const float C12 = Bc2 * cs.x + Bs2 * cs.y;
    const float C22 = bb2 * cs.x * cs.x - bE2 * cs.y * cs.y;

    __syncthreads();

    float a0 = 0.0f, a1 = 0.0f, a2 = 0.0f, a3 = 0.0f;
    #pragma unroll 8
    for (int i = 0; i < NTH; i += 4) {
        float4 n0 = nd[i + 0];
        float4 n1 = nd[i + 1];
        float4 n2 = nd[i + 2];
        float4 n3 = nd[i + 3];
        float t0 = fmaf(A2, n0.x, fmaf(C12, n0.y, fmaf(C22, n0.z, nM02)));
        float t1 = fmaf(A2, n1.x, fmaf(C12, n1.y, fmaf(C22, n1.z, nM02)));
        float t2 = fmaf(A2, n2.x, fmaf(C12, n2.y, fmaf(C22, n2.z, nM02)));
        float t3 = fmaf(A2, n3.x, fmaf(C12, n3.y, fmaf(C22, n3.z, nM02)));
        a0 = fmaf(n0.w, exp2f(t0), a0);
        a1 = fmaf(n1.w, exp2f(t1), a1);
        a2 = fmaf(n2.w, exp2f(t2), a2);
        a3 = fmaf(n3.w, exp2f(t3), a3);
    }
    float sum = (a0 + a1) + (a2 + a3);

    #pragma unroll
    for (int o = 16; o > 0; o >>= 1)
        sum += __shfl_xor_sync(0xffffffffu, sum, o);
    if ((tid & 31) == 0) red[tid >> 5] = sum;
    __syncthreads();

    if (tid == 0) {
        float tot = 0.0f;
        #pragma unroll
        for (int wI = 0; wI < NPH / 32; ++wI) tot += red[wI];
        const float DPHI = 6.2831853071795864769f / (float)NPH;
        // logC = M0 + log(sum_ij w_i*dphi*exp(expo_ij - M0))
        float logC = s[6] + logf(tot * DPHI);
        // return -logp = logC - (kappa*ngx + beta*(g2^2 - eta*g3^2))
        out[b] = logC - s[7];
    }
}

// ---------------------------------------------------------------------------
// Inputs (metadata order): x[B,3], theta, phi, psi, kappa, beta, eta, alpha,
// rho (each [B], float32). Output: [B] float32.
// ---------------------------------------------------------------------------
extern "C" void kernel_launch(void* const* d_in, const int* in_sizes, int n_in,
                              void* d_out, int out_size)
{
    const float* x     = (const float*)d_in[0];
    const float* theta = (const float*)d_in[1];
    const float* phi   = (const float*)d_in[2];
    const float* psi   = (const float*)d_in[3];
    const float* kappa = (const float*)d_in[4];
    const float* beta  = (const float*)d_in[5];
    const float* eta   = (const float*)d_in[6];
    const float* alpha = (const float*)d_in[7];
    const float* rho   = (const float*)d_in[8];

    int B = in_sizes[1];   // theta element count
    if (B > MAXB) B = MAXB;

    fb8_init_kernel<<<1, 256>>>();
    fb8_prep_kernel<<<(B + 127) / 128, 128>>>(x, theta, phi, psi, kappa, beta,
                                              eta, alpha, rho, B);
    fb8_main_kernel<<<B, NPH>>>((float*)d_out);
}

// round 14
// speedup vs baseline: 1.9831x; 1.9831x over previous
#include <cuda_runtime.h>
#include <math.h>
#include <math_constants.h>

#define NTH    128   // Gauss-Legendre nodes in theta (identical to reference)
#define NPH_K  64    // phi grid (trapezoid; equals the reference's 256-pt
                     // trapezoid to ~1e-9 by spectral convergence)
#define MAXB   8192

// Tables in __device__ globals (no allocation allowed).
__device__ float4 g_nodes[NTH];    // {u, s=sqrt(1-u^2), s2=1-u^2, w}
__device__ float2 g_phi[NPH_K];    // {cos(phi_j), sin(phi_j)}

// ---------------------------------------------------------------------------
// Init (256 threads, 1 block): 128-pt Gauss-Legendre nodes/weights.
//   Stage 1: fp32 Newton warm start (3 iters) -> x to ~1e-7.
//   Stage 2: 2 fp64 Newton refinements. Each evaluation splits the 127-step
//     Legendre recurrence across two threads to halve the DFMA critical path:
//       thread t        (t<128): propagates (P0,P1) through j=2..65 -> P64,P65
//       thread t+128         : builds the 2x2 transfer map (P65,P64)->(P128,P127)
//                              for j=66..128 via two unit-IC chains (linearity)
//     Combine, dp = n(x*P128 - P127)/(x^2-1), Newton update.
//   Weight uses dp evaluated at x with error ~3e-11 -> weight rel err ~3e-7
//   even at the endpoint nodes (the fp32-only version had ~1e-4..1e-3 there,
//   which caused the R13 failure).
// ---------------------------------------------------------------------------
__global__ void fb8_init_kernel() {
    __shared__ float  c1f[NTH + 1], c2f[NTH + 1];
    __shared__ double c1d[NTH + 1], c2d[NTH + 1];
    __shared__ double xs[NTH];
    __shared__ double pv[NTH][2];   // P65, P64
    __shared__ double mv[NTH][4];   // U128, U127, V128, V127

    const int t    = threadIdx.x;
    const int node = t & (NTH - 1);

    for (int j = t; j <= NTH; j += 256) {
        if (j >= 2) {
            double dj = (double)j;
            double a  = (2.0 * dj - 1.0) / dj;
            double bb = (dj - 1.0) / dj;
            c1d[j] = a;  c2d[j] = bb;
            c1f[j] = (float)a;  c2f[j] = (float)bb;
        }
    }
    __syncthreads();

    // --- Stage 1: fp32 warm start (threads 0..127) ---
    if (t < NTH) {
        const float n = (float)NTH;
        float x = cosf((float)CUDART_PI * ((float)t + 0.75f) / (n + 0.5f));
        #pragma unroll 1
        for (int it = 0; it < 3; ++it) {
            float p0 = 1.0f, p1 = x;
            #pragma unroll 4
            for (int j = 2; j <= NTH; ++j) {
                float p2 = fmaf(c1f[j] * x, p1, -(c2f[j] * p0));
                p0 = p1;  p1 = p2;
            }
            float s2 = (1.0f - x) * (1.0f + x);
            float dp = n * fmaf(x, p1, -p0) / (-s2);
            x -= p1 / dp;
        }
        xs[t] = (double)x;
    }
    __syncthreads();

    // --- Stage 2: two fp64 Newton refinements, split critical path ---
    double dpn = 1.0;
    #pragma unroll 1
    for (int it = 0; it < 2; ++it) {
        double x = xs[node];
        if (t < NTH) {
            double p0 = 1.0, p1 = x;
            #pragma unroll 4
            for (int j = 2; j <= 65; ++j) {
                double p2 = fma(c1d[j] * x, p1, -(c2d[j] * p0));
                p0 = p1;  p1 = p2;
            }
            pv[t][0] = p1;   // P65
            pv[t][1] = p0;   // P64
        } else {
            double u1 = 1.0, u0 = 0.0;   // IC: (q65,q64) = (1,0)
            double v1 = 0.0, v0 = 1.0;   // IC: (q65,q64) = (0,1)
            #pragma unroll 4
            for (int j = 66; j <= NTH; ++j) {
                double ax = c1d[j] * x, bj = c2d[j];
                double u2 = fma(ax, u1, -(bj * u0));
                double v2 = fma(ax, v1, -(bj * v0));
                u0 = u1;  u1 = u2;
                v0 = v1;  v1 = v2;
            }
            mv[node][0] = u1;  mv[node][1] = u0;
            mv[node][2] = v1;  mv[node][3] = v0;
        }
        __syncthreads();
        if (t < NTH) {
            double P65 = pv[t][0], P64 = pv[t][1];
            double p128 = mv[t][0] * P65 + mv[t][2] * P64;
            double p127 = mv[t][1] * P65 + mv[t][3] * P64;
            dpn = (double)NTH * (x * p128 - p127) / ((x - 1.0) * (x + 1.0));
            xs[t] = x - p128 / dpn;
        }
        __syncthreads();
    }

    if (t < NTH) {
        double xr = xs[t];
        double s2 = (1.0 - xr) * (1.0 + xr);
        double w  = 2.0 / (s2 * dpn * dpn);
        g_nodes[t] = make_float4((float)xr, (float)sqrt(s2),
                                 (float)s2, (float)w);
    }
    if (t < NPH_K) {
        double a = (double)t * (2.0 * CUDART_PI / (double)NPH_K);
        g_phi[t] = make_float2((float)cos(a), (float)sin(a));
    }
}

__device__ __forceinline__ float ex2f(float x) {
    float r;
    asm("ex2.approx.ftz.f32 %0, %1;" : "=f"(r) : "f"(x));
    return r;
}

// ---------------------------------------------------------------------------
// Main: one block per batch element. Warp 0 computes the per-batch scalars
// redundantly (no shuffles; same warp cost as one thread), publishes to
// shared. Then 256 threads = 64 phi columns x 4 theta-chunks of 32 GL nodes:
//   expo(log2) = A2*u + C12*s + C22*s2 - M02,   sum += w * exp2(expo)
// Single pass (analytic upper bound M0 keeps every exponent <= 0), block
// reduction, out[b] = M0 + ln(sum*dphi) - base.
// ---------------------------------------------------------------------------
__global__ __launch_bounds__(256)
void fb8_main_kernel(
    const float* __restrict__ x,
    const float* __restrict__ theta, const float* __restrict__ phi,
    const float* __restrict__ psi,   const float* __restrict__ kappa,
    const float* __restrict__ beta,  const float* __restrict__ eta,
    const float* __restrict__ alpha, const float* __restrict__ rho,
    float* __restrict__ out)
{
    __shared__ float4 nd[NTH];
    __shared__ float  s8[8];          // A2,Bc2,Bs2,bb2,bE2,M02,M0,base
    __shared__ float  red[256 / 32];

    const int b   = blockIdx.x;
    const int tid = threadIdx.x;

    if (tid < NTH) nd[tid] = g_nodes[tid];

    if (tid < 32) {
        float x0 = x[3 * b + 0], x1 = x[3 * b + 1], x2 = x[3 * b + 2];
        float st, ct, sp, cp, sq, cq, sa, ca, sr, cr;
        sincosf(theta[b], &st, &ct);
        sincosf(phi[b],   &sp, &cp);
        sincosf(psi[b],   &sq, &cq);
        sincosf(alpha[b], &sa, &ca);
        sincosf(rho[b],   &sr, &cr);

        // Gamma = H(theta,phi) @ K(psi); project x onto its columns.
        float g1 = x0 * ct         + x1 * (st * cp)              + x2 * (st * sp);
        float g2 = x0 * (-st * cq) + x1 * (ct * cp * cq - sp * sq)
                                   + x2 * (ct * sp * cq + cp * sq);
        float g3 = x0 * (st * sq)  + x1 * (-ct * cp * sq - sp * cq)
                                   + x2 * (cp * cq - ct * sp * sq);

        float nu0 = ca, nu1 = sa * cr, nu2 = sa * sr;
        float ngx = nu0 * g1 + nu1 * g2 + nu2 * g3;

        float kap = kappa[b], bet = beta[b], et = eta[b];
        float A  = kap * nu0;
        float Bc = kap * nu1;
        float Bs = kap * nu2;
        float bb = bet;
        float bE = bet * et;

        // Upper bound of expo over the sphere: exact logsumexp shift.
        float M0 = fabsf(A) + sqrtf(Bc * Bc + Bs * Bs)
                 + fmaxf(0.0f, fmaxf(bb, -bE));
        float bas = kap * ngx + bet * (g2 * g2 - et * g3 * g3);

        if (tid == 0) {
            const float L2E = 1.4426950408889634074f;
            s8[0] = A  * L2E;
            s8[1] = Bc * L2E;
            s8[2] = Bs * L2E;
            s8[3] = bb * L2E;
            s8[4] = bE * L2E;
            s8[5] = M0 * L2E;
            s8[6] = M0;
            s8[7] = bas;
        }
    }
    __syncthreads();

    const float A2   =  s8[0];
    const float nM02 = -s8[5];
    const int   pj   = tid & (NPH_K - 1);    // phi column, 0..63
    const int   tb   = (tid >> 6) * 32;      // theta chunk base

    const float2 cs  = g_phi[pj];
    const float  C12 = s8[1] * cs.x + s8[2] * cs.y;
    const float  C22 = s8[3] * cs.x * cs.x - s8[4] * cs.y * cs.y;

    float a0 = 0.0f, a1 = 0.0f, a2 = 0.0f, a3 = 0.0f;
    #pragma unroll
    for (int i = 0; i < 32; i += 4) {
        float4 n0 = nd[tb + i + 0];
        float4 n1 = nd[tb + i + 1];
        float4 n2 = nd[tb + i + 2];
        float4 n3 = nd[tb + i + 3];
        float t0 = fmaf(A2, n0.x, fmaf(C12, n0.y, fmaf(C22, n0.z, nM02)));
        float t1 = fmaf(A2, n1.x, fmaf(C12, n1.y, fmaf(C22, n1.z, nM02)));
        float t2 = fmaf(A2, n2.x, fmaf(C12, n2.y, fmaf(C22, n2.z, nM02)));
        float t3 = fmaf(A2, n3.x, fmaf(C12, n3.y, fmaf(C22, n3.z, nM02)));
        a0 = fmaf(n0.w, ex2f(t0), a0);
        a1 = fmaf(n1.w, ex2f(t1), a1);
        a2 = fmaf(n2.w, ex2f(t2), a2);
        a3 = fmaf(n3.w, ex2f(t3), a3);
    }
    float sum = (a0 + a1) + (a2 + a3);

    #pragma unroll
    for (int o = 16; o > 0; o >>= 1)
        sum += __shfl_xor_sync(0xffffffffu, sum, o);
    if ((tid & 31) == 0) red[tid >> 5] = sum;
    __syncthreads();

    if (tid == 0) {
        float tot = 0.0f;
        #pragma unroll
        for (int wI = 0; wI < 256 / 32; ++wI) tot += red[wI];
        const float DPHI = 6.2831853071795864769f / (float)NPH_K;
        float logC = s8[6] + logf(tot * DPHI);
        out[b] = logC - s8[7];       // -logp
    }
}

// ---------------------------------------------------------------------------
// Inputs (metadata order): x[B,3], theta, phi, psi, kappa, beta, eta, alpha,
// rho (each [B], float32). Output: [B] float32.
// ---------------------------------------------------------------------------
extern "C" void kernel_launch(void* const* d_in, const int* in_sizes, int n_in,
                              void* d_out, int out_size)
{
    const float* x     = (const float*)d_in[0];
    const float* theta = (const float*)d_in[1];
    const float* phi   = (const float*)d_in[2];
    const float* psi   = (const float*)d_in[3];
    const float* kappa = (const float*)d_in[4];
    const float* beta  = (const float*)d_in[5];
    const float* eta   = (const float*)d_in[6];
    const float* alpha = (const float*)d_in[7];
    const float* rho   = (const float*)d_in[8];

    int B = in_sizes[1];   // theta element count
    if (B > MAXB) B = MAXB;

    fb8_init_kernel<<<1, 256>>>();
    fb8_main_kernel<<<B, 256>>>(x, theta, phi, psi, kappa, beta, eta,
                                alpha, rho, (float*)d_out);
}

// round 15
// speedup vs baseline: 3.0051x; 1.5154x over previous
#include <cuda_runtime.h>
#include <math.h>
#include <math_constants.h>

#define NTH    128   // Gauss-Legendre nodes in theta (identical to reference)
#define NPH_K  64    // phi trapezoid (== reference's 256-pt rule to ~1e-9)
#define BPB    4     // batch elements per block in the main kernel
#define MAXB   8192

// Tables in __device__ globals (no allocation allowed).
__device__ float4 g_nodes[NTH];    // {u, s=sqrt(1-u^2), s2=1-u^2, w}
__device__ float2 g_phi[NPH_K];    // {cos(phi_j), sin(phi_j)}

// ---------------------------------------------------------------------------
// Init (256 threads, 1 block): 128-pt Gauss-Legendre nodes/weights.
//  Stage 1: fp32 Newton warm start (3 iters) -> x0 accurate to fp32 repr
//           (~6e-8).
//  Stage 2: ONE fp64 evaluation, critical path split across two threads:
//    t<128 : (P0,P1) -> P64,P65 over j=2..65
//    t>=128: 2x2 transfer map (P65,P64)->(P128,P127) over j=66..128
//            via two unit-IC chains (recurrence is linear)
//    then: dp0 = n(x0*P128 - P127)/(x0^2-1)
//          x1  = x0 - P128/dp0                        (node err ~1e-11)
//          P'' = (2*x0*dp0 - n(n+1)*P128)/(1-x0^2)    (Legendre ODE)
//          dp1 = dp0 + P''*(x1-x0)                    (weight rel err ~1e-7,
//                                                      endpoint-safe)
//          w   = 2/((1-x1^2)*dp1^2)
// ---------------------------------------------------------------------------
__global__ void fb8_init_kernel() {
    __shared__ float  c1f[NTH + 1], c2f[NTH + 1];
    __shared__ double c1d[NTH + 1], c2d[NTH + 1];
    __shared__ double xs[NTH];
    __shared__ double pv[NTH][2];   // P65, P64
    __shared__ double mv[NTH][4];   // U128, U127, V128, V127

    const int t    = threadIdx.x;
    const int node = t & (NTH - 1);

    for (int j = t; j <= NTH; j += 256) {
        if (j >= 2) {
            double dj = (double)j;
            double a  = (2.0 * dj - 1.0) / dj;
            double bb = (dj - 1.0) / dj;
            c1d[j] = a;  c2d[j] = bb;
            c1f[j] = (float)a;  c2f[j] = (float)bb;
        }
    }
    __syncthreads();

    // --- Stage 1: fp32 warm start (threads 0..127) ---
    if (t < NTH) {
        const float n = (float)NTH;
        float x = cosf((float)CUDART_PI * ((float)t + 0.75f) / (n + 0.5f));
        #pragma unroll 1
        for (int it = 0; it < 3; ++it) {
            float p0 = 1.0f, p1 = x;
            #pragma unroll 4
            for (int j = 2; j <= NTH; ++j) {
                float p2 = fmaf(c1f[j] * x, p1, -(c2f[j] * p0));
                p0 = p1;  p1 = p2;
            }
            float s2 = (1.0f - x) * (1.0f + x);
            float dp = n * fmaf(x, p1, -p0) / (-s2);
            x -= p1 / dp;
        }
        xs[t] = (double)x;
    }
    __syncthreads();

    // --- Stage 2: single split fp64 evaluation + ODE-corrected derivative ---
    {
        double x = xs[node];
        if (t < NTH) {
            double p0 = 1.0, p1 = x;
            #pragma unroll 4
            for (int j = 2; j <= 65; ++j) {
                double p2 = fma(c1d[j] * x, p1, -(c2d[j] * p0));
                p0 = p1;  p1 = p2;
            }
            pv[t][0] = p1;   // P65
            pv[t][1] = p0;   // P64
        } else {
            double u1 = 1.0, u0 = 0.0;   // IC (q65,q64)=(1,0)
            double v1 = 0.0, v0 = 1.0;   // IC (q65,q64)=(0,1)
            #pragma unroll 4
            for (int j = 66; j <= NTH; ++j) {
                double ax = c1d[j] * x, bj = c2d[j];
                double u2 = fma(ax, u1, -(bj * u0));
                double v2 = fma(ax, v1, -(bj * v0));
                u0 = u1;  u1 = u2;
                v0 = v1;  v1 = v2;
            }
            mv[node][0] = u1;  mv[node][1] = u0;
            mv[node][2] = v1;  mv[node][3] = v0;
        }
        __syncthreads();

        if (t < NTH) {
            const double n = (double)NTH;
            double P65 = pv[t][0], P64 = pv[t][1];
            double p128 = mv[t][0] * P65 + mv[t][2] * P64;
            double p127 = mv[t][1] * P65 + mv[t][3] * P64;
            double s2x = (1.0 - x) * (1.0 + x);
            double dp0 = n * (x * p128 - p127) / (-(-s2x));   // n(xP-P')/( -(x^2-1) )
            dp0 = n * (x * p128 - p127) / s2x * 1.0;          // keep simple
            // (dp0 = n*(x*P128 - P127)/(x^2 - 1) -> note sign:)
            dp0 = n * (x * p128 - p127) / ((x - 1.0) * (x + 1.0));
            double dx  = -p128 / dp0;
            double x1  = x + dx;
            double ppp = (2.0 * x * dp0 - (n * (n + 1.0)) * p128) / s2x;
            double dp1 = dp0 + ppp * dx;
            double s2  = (1.0 - x1) * (1.0 + x1);
            double w   = 2.0 / (s2 * dp1 * dp1);
            g_nodes[t] = make_float4((float)x1, (float)sqrt(s2),
                                     (float)s2, (float)w);
        }
    }

    if (t < NPH_K) {
        double a = (double)t * (2.0 * CUDART_PI / (double)NPH_K);
        g_phi[t] = make_float2((float)cos(a), (float)sin(a));
    }
}

__device__ __forceinline__ float ex2f(float x) {
    float r;
    asm("ex2.approx.ftz.f32 %0, %1;" : "=f"(r) : "f"(x));
    return r;
}

// ---------------------------------------------------------------------------
// Main: BPB=4 batch elements per block, 256 threads.
//   Prologue: warps 0..3 compute batch (b0+warp)'s scalars redundantly across
//   lanes (lane 0 publishes); warps 4..7 stage the node/phi tables to shared.
//   Body: 256 threads = 64 phi columns x 4 theta-chunks of 32 nodes; the 4
//   batches are interleaved per node (4 independent FMA->EX2 chains, one
//   broadcast LDS.128 per node serving all 4):
//     expo(log2) = A2*u + C12*s + C22*s2 - M02,  acc += w * exp2(expo)
//   Single pass (analytic bound M0 keeps exponents <= 0), 4 block reductions,
//   out[b] = M0 + ln(sum*dphi) - base.
// ---------------------------------------------------------------------------
__global__ __launch_bounds__(256)
void fb8_main_kernel(
    const float* __restrict__ x,
    const float* __restrict__ theta, const float* __restrict__ phi,
    const float* __restrict__ psi,   const float* __restrict__ kappa,
    const float* __restrict__ beta,  const float* __restrict__ eta,
    const float* __restrict__ alpha, const float* __restrict__ rho,
    float* __restrict__ out, int B)
{
    __shared__ float4 nd[NTH];
    __shared__ float2 ph[NPH_K];
    __shared__ float  s8[BPB][8];     // A2,Bc2,Bs2,bb2,bE2,M02,M0,base
    __shared__ float4 redv[8];        // per-warp partials, one lane per batch

    const int tid = threadIdx.x;
    const int b0  = blockIdx.x * BPB;

    if (tid >= 128) {
        int i = tid - 128;
        nd[i] = g_nodes[i];
        if (i < NPH_K) ph[i] = g_phi[i];
    } else {
        const int w = tid >> 5;           // warp 0..3 -> batch b0+w
        const int b = b0 + w;
        if (b < B) {
            float x0 = x[3 * b + 0], x1v = x[3 * b + 1], x2v = x[3 * b + 2];
            float st, ct, sp, cp, sq, cq, sa, ca, sr, cr;
            sincosf(theta[b], &st, &ct);
            sincosf(phi[b],   &sp, &cp);
            sincosf(psi[b],   &sq, &cq);
            sincosf(alpha[b], &sa, &ca);
            sincosf(rho[b],   &sr, &cr);

            // Gamma = H(theta,phi) @ K(psi); project x onto its columns.
            float g1 = x0 * ct         + x1v * (st * cp)              + x2v * (st * sp);
            float g2 = x0 * (-st * cq) + x1v * (ct * cp * cq - sp * sq)
                                       + x2v * (ct * sp * cq + cp * sq);
            float g3 = x0 * (st * sq)  + x1v * (-ct * cp * sq - sp * cq)
                                       + x2v * (cp * cq - ct * sp * sq);

            float nu0 = ca, nu1 = sa * cr, nu2 = sa * sr;
            float ngx = nu0 * g1 + nu1 * g2 + nu2 * g3;

            float kap = kappa[b], bet = beta[b], et = eta[b];
            float A  = kap * nu0;
            float Bc = kap * nu1;
            float Bs = kap * nu2;
            float bb = bet;
            float bE = bet * et;

            // Exact logsumexp shift: upper bound of expo over the sphere.
            float M0  = fabsf(A) + sqrtf(Bc * Bc + Bs * Bs)
                      + fmaxf(0.0f, fmaxf(bb, -bE));
            float bas = kap * ngx + bet * (g2 * g2 - et * g3 * g3);

            if ((tid & 31) == 0) {
                const float L2E = 1.4426950408889634074f;
                s8[w][0] = A  * L2E;
                s8[w][1] = Bc * L2E;
                s8[w][2] = Bs * L2E;
                s8[w][3] = bb * L2E;
                s8[w][4] = bE * L2E;
                s8[w][5] = M0 * L2E;
                s8[w][6] = M0;
                s8[w][7] = bas;
            }
        }
    }
    __syncthreads();

    const int pj = tid & (NPH_K - 1);       // phi column 0..63
    const int tb = (tid >> 6) << 5;         // theta chunk base: 0,32,64,96

    const float2 cs = ph[pj];
    const float  cc = cs.x * cs.x, ssq = cs.y * cs.y;

    float A2[BPB], C12[BPB], C22[BPB], nM0[BPB], acc[BPB];
    #pragma unroll
    for (int k = 0; k < BPB; ++k) {
        A2[k]  = s8[k][0];
        C12[k] = fmaf(s8[k][1], cs.x, s8[k][2] * cs.y);
        C22[k] = fmaf(s8[k][3], cc, -(s8[k][4] * ssq));
        nM0[k] = -s8[k][5];
        acc[k] = 0.0f;
    }

    #pragma unroll 4
    for (int i = 0; i < 32; ++i) {
        float4 n = nd[tb + i];
        #pragma unroll
        for (int k = 0; k < BPB; ++k) {
            float tt = fmaf(A2[k], n.x,
                       fmaf(C12[k], n.y,
                       fmaf(C22[k], n.z, nM0[k])));
            acc[k] = fmaf(n.w, ex2f(tt), acc[k]);
        }
    }

    #pragma unroll
    for (int o = 16; o > 0; o >>= 1) {
        #pragma unroll
        for (int k = 0; k < BPB; ++k)
            acc[k] += __shfl_xor_sync(0xffffffffu, acc[k], o);
    }
    if ((tid & 31) == 0)
        redv[tid >> 5] = make_float4(acc[0], acc[1], acc[2], acc[3]);
    __syncthreads();

    if (tid < BPB && (b0 + tid) < B) {
        float tot = 0.0f;
        #pragma unroll
        for (int w = 0; w < 8; ++w) {
            float4 r = redv[w];
            tot += (tid == 0) ? r.x : (tid == 1) ? r.y : (tid == 2) ? r.z : r.w;
        }
        const float DPHI = 6.2831853071795864769f / (float)NPH_K;
        float logC = s8[tid][6] + logf(tot * DPHI);
        out[b0 + tid] = logC - s8[tid][7];     // -logp
    }
}

// ---------------------------------------------------------------------------
// Inputs (metadata order): x[B,3], theta, phi, psi, kappa, beta, eta, alpha,
// rho (each [B], float32). Output: [B] float32.
// ---------------------------------------------------------------------------
extern "C" void kernel_launch(void* const* d_in, const int* in_sizes, int n_in,
                              void* d_out, int out_size)
{
    const float* x     = (const float*)d_in[0];
    const float* theta = (const float*)d_in[1];
    const float* phi   = (const float*)d_in[2];
    const float* psi   = (const float*)d_in[3];
    const float* kappa = (const float*)d_in[4];
    const float* beta  = (const float*)d_in[5];
    const float* eta   = (const float*)d_in[6];
    const float* alpha = (const float*)d_in[7];
    const float* rho   = (const float*)d_in[8];

    int B = in_sizes[1];   // theta element count
    if (B > MAXB) B = MAXB;

    fb8_init_kernel<<<1, 256>>>();
    int grid = (B + BPB - 1) / BPB;
    fb8_main_kernel<<<grid, 256>>>(x, theta, phi, psi, kappa, beta, eta,
                                   alpha, rho, (float*)d_out, B);
}

// round 16
// speedup vs baseline: 3.0250x; 1.0066x over previous
#include <cuda_runtime.h>
#include <math.h>
#include <math_constants.h>

#define NTH    128   // Gauss-Legendre nodes in theta (identical to reference)
#define NPH_K  64    // phi trapezoid (== reference's 256-pt rule to ~1e-9)
#define BPB    4     // batch elements per block in the main kernel
#define MAXB   8192

// Tables in __device__ globals (no allocation allowed).
__device__ float4 g_nodes[NTH];    // {u, s=sqrt(1-u^2), s2=1-u^2, w}
__device__ float2 g_phi[NPH_K];    // {cos(phi_j), sin(phi_j)}

// ---------------------------------------------------------------------------
// Init (256 threads, 1 block): 128-pt Gauss-Legendre nodes/weights.
//  Stage 1: fp32 Newton warm start (3 iters) -> x0 accurate to fp32 repr
//           (~6e-8).
//  Stage 2: ONE fp64 evaluation, critical path split across two threads:
//    t<128 : (P0,P1) -> P64,P65 over j=2..65
//    t>=128: 2x2 transfer map (P65,P64)->(P128,P127) over j=66..128
//            via two unit-IC chains (recurrence is linear)
//    then: dp0 = n(x0*P128 - P127)/(x0^2-1)
//          x1  = x0 - P128/dp0                        (node err ~1e-11)
//          P'' = (2*x0*dp0 - n(n+1)*P128)/(1-x0^2)    (Legendre ODE)
//          dp1 = dp0 + P''*(x1-x0)                    (weight rel err ~1e-7,
//                                                      endpoint-safe)
//          w   = 2/((1-x1^2)*dp1^2)
// ---------------------------------------------------------------------------
__global__ void fb8_init_kernel() {
    __shared__ float  c1f[NTH + 1], c2f[NTH + 1];
    __shared__ double c1d[NTH + 1], c2d[NTH + 1];
    __shared__ double xs[NTH];
    __shared__ double pv[NTH][2];   // P65, P64
    __shared__ double mv[NTH][4];   // U128, U127, V128, V127

    const int t    = threadIdx.x;
    const int node = t & (NTH - 1);

    for (int j = t; j <= NTH; j += 256) {
        if (j >= 2) {
            double dj = (double)j;
            double a  = (2.0 * dj - 1.0) / dj;
            double bb = (dj - 1.0) / dj;
            c1d[j] = a;  c2d[j] = bb;
            c1f[j] = (float)a;  c2f[j] = (float)bb;
        }
    }
    __syncthreads();

    // --- Stage 1: fp32 warm start (threads 0..127) ---
    if (t < NTH) {
        const float n = (float)NTH;
        float x = cosf((float)CUDART_PI * ((float)t + 0.75f) / (n + 0.5f));
        #pragma unroll 1
        for (int it = 0; it < 3; ++it) {
            float p0 = 1.0f, p1 = x;
            #pragma unroll 4
            for (int j = 2; j <= NTH; ++j) {
                float p2 = fmaf(c1f[j] * x, p1, -(c2f[j] * p0));
                p0 = p1;  p1 = p2;
            }
            float s2 = (1.0f - x) * (1.0f + x);
            float dp = n * fmaf(x, p1, -p0) / (-s2);
            x -= p1 / dp;
        }
        xs[t] = (double)x;
    }
    __syncthreads();

    // --- Stage 2: single split fp64 evaluation + ODE-corrected derivative ---
    {
        double x = xs[node];
        if (t < NTH) {
            double p0 = 1.0, p1 = x;
            #pragma unroll 4
            for (int j = 2; j <= 65; ++j) {
                double p2 = fma(c1d[j] * x, p1, -(c2d[j] * p0));
                p0 = p1;  p1 = p2;
            }
            pv[t][0] = p1;   // P65
            pv[t][1] = p0;   // P64
        } else {
            double u1 = 1.0, u0 = 0.0;   // IC (q65,q64)=(1,0)
            double v1 = 0.0, v0 = 1.0;   // IC (q65,q64)=(0,1)
            #pragma unroll 4
            for (int j = 66; j <= NTH; ++j) {
                double ax = c1d[j] * x, bj = c2d[j];
                double u2 = fma(ax, u1, -(bj * u0));
                double v2 = fma(ax, v1, -(bj * v0));
                u0 = u1;  u1 = u2;
                v0 = v1;  v1 = v2;
            }
            mv[node][0] = u1;  mv[node][1] = u0;
            mv[node][2] = v1;  mv[node][3] = v0;
        }
        __syncthreads();

        if (t < NTH) {
            const double n = (double)NTH;
            double P65 = pv[t][0], P64 = pv[t][1];
            double p128 = mv[t][0] * P65 + mv[t][2] * P64;
            double p127 = mv[t][1] * P65 + mv[t][3] * P64;
            double s2x = (1.0 - x) * (1.0 + x);
            double dp0 = n * (x * p128 - p127) / (-(-s2x));   // n(xP-P')/( -(x^2-1) )
            dp0 = n * (x * p128 - p127) / s2x * 1.0;          // keep simple
            // (dp0 = n*(x*P128 - P127)/(x^2 - 1) -> note sign:)
            dp0 = n * (x * p128 - p127) / ((x - 1.0) * (x + 1.0));
            double dx  = -p128 / dp0;
            double x1  = x + dx;
            double ppp = (2.0 * x * dp0 - (n * (n + 1.0)) * p128) / s2x;
            double dp1 = dp0 + ppp * dx;
            double s2  = (1.0 - x1) * (1.0 + x1);
            double w   = 2.0 / (s2 * dp1 * dp1);
            g_nodes[t] = make_float4((float)x1, (float)sqrt(s2),
                                     (float)s2, (float)w);
        }
    }

    if (t < NPH_K) {
        double a = (double)t * (2.0 * CUDART_PI / (double)NPH_K);
        g_phi[t] = make_float2((float)cos(a), (float)sin(a));
    }
}

__device__ __forceinline__ float ex2f(float x) {
    float r;
    asm("ex2.approx.ftz.f32 %0, %1;" : "=f"(r) : "f"(x));
    return r;
}

// ---------------------------------------------------------------------------
// Main: BPB=4 batch elements per block, 256 threads.
//   Prologue: warps 0..3 compute batch (b0+warp)'s scalars redundantly across
//   lanes (lane 0 publishes); warps 4..7 stage the node/phi tables to shared.
//   Body: 256 threads = 64 phi columns x 4 theta-chunks of 32 nodes; the 4
//   batches are interleaved per node (4 independent FMA->EX2 chains, one
//   broadcast LDS.128 per node serving all 4):
//     expo(log2) = A2*u + C12*s + C22*s2 - M02,  acc += w * exp2(expo)
//   Single pass (analytic bound M0 keeps exponents <= 0), 4 block reductions,
//   out[b] = M0 + ln(sum*dphi) - base.
// ---------------------------------------------------------------------------
__global__ __launch_bounds__(256)
void fb8_main_kernel(
    const float* __restrict__ x,
    const float* __restrict__ theta, const float* __restrict__ phi,
    const float* __restrict__ psi,   const float* __restrict__ kappa,
    const float* __restrict__ beta,  const float* __restrict__ eta,
    const float* __restrict__ alpha, const float* __restrict__ rho,
    float* __restrict__ out, int B)
{
    __shared__ float4 nd[NTH];
    __shared__ float2 ph[NPH_K];
    __shared__ float  s8[BPB][8];     // A2,Bc2,Bs2,bb2,bE2,M02,M0,base
    __shared__ float4 redv[8];        // per-warp partials, one lane per batch

    const int tid = threadIdx.x;
    const int b0  = blockIdx.x * BPB;

    if (tid >= 128) {
        int i = tid - 128;
        nd[i] = g_nodes[i];
        if (i < NPH_K) ph[i] = g_phi[i];
    } else {
        const int w = tid >> 5;           // warp 0..3 -> batch b0+w
        const int b = b0 + w;
        if (b < B) {
            float x0 = x[3 * b + 0], x1v = x[3 * b + 1], x2v = x[3 * b + 2];
            float st, ct, sp, cp, sq, cq, sa, ca, sr, cr;
            sincosf(theta[b], &st, &ct);
            sincosf(phi[b],   &sp, &cp);
            sincosf(psi[b],   &sq, &cq);
            sincosf(alpha[b], &sa, &ca);
            sincosf(rho[b],   &sr, &cr);

            // Gamma = H(theta,phi) @ K(psi); project x onto its columns.
            float g1 = x0 * ct         + x1v * (st * cp)              + x2v * (st * sp);
            float g2 = x0 * (-st * cq) + x1v * (ct * cp * cq - sp * sq)
                                       + x2v * (ct * sp * cq + cp * sq);
            float g3 = x0 * (st * sq)  + x1v * (-ct * cp * sq - sp * cq)
                                       + x2v * (cp * cq - ct * sp * sq);

            float nu0 = ca, nu1 = sa * cr, nu2 = sa * sr;
            float ngx = nu0 * g1 + nu1 * g2 + nu2 * g3;

            float kap = kappa[b], bet = beta[b], et = eta[b];
            float A  = kap * nu0;
            float Bc = kap * nu1;
            float Bs = kap * nu2;
            float bb = bet;
            float bE = bet * et;

            // Exact logsumexp shift: upper bound of expo over the sphere.
            float M0  = fabsf(A) + sqrtf(Bc * Bc + Bs * Bs)
                      + fmaxf(0.0f, fmaxf(bb, -bE));
            float bas = kap * ngx + bet * (g2 * g2 - et * g3 * g3);

            if ((tid & 31) == 0) {
                const float L2E = 1.4426950408889634074f;
                s8[w][0] = A  * L2E;
                s8[w][1] = Bc * L2E;
                s8[w][2] = Bs * L2E;
                s8[w][3] = bb * L2E;
                s8[w][4] = bE * L2E;
                s8[w][5] = M0 * L2E;
                s8[w][6] = M0;
                s8[w][7] = bas;
            }
        }
    }
    __syncthreads();

    const int pj = tid & (NPH_K - 1);       // phi column 0..63
    const int tb = (tid >> 6) << 5;         // theta chunk base: 0,32,64,96

    const float2 cs = ph[pj];
    const float  cc = cs.x * cs.x, ssq = cs.y * cs.y;

    float A2[BPB], C12[BPB], C22[BPB], nM0[BPB], acc[BPB];
    #pragma unroll
    for (int k = 0; k < BPB; ++k) {
        A2[k]  = s8[k][0];
        C12[k] = fmaf(s8[k][1], cs.x, s8[k][2] * cs.y);
        C22[k] = fmaf(s8[k][3], cc, -(s8[k][4] * ssq));
        nM0[k] = -s8[k][5];
        acc[k] = 0.0f;
    }

    #pragma unroll 4
    for (int i = 0; i < 32; ++i) {
        float4 n = nd[tb + i];
        #pragma unroll
        for (int k = 0; k < BPB; ++k) {
            float tt = fmaf(A2[k], n.x,
                       fmaf(C12[k], n.y,
                       fmaf(C22[k], n.z, nM0[k])));
            acc[k] = fmaf(n.w, ex2f(tt), acc[k]);
        }
    }

    #pragma unroll
    for (int o = 16; o > 0; o >>= 1) {
        #pragma unroll
        for (int k = 0; k < BPB; ++k)
            acc[k] += __shfl_xor_sync(0xffffffffu, acc[k], o);
    }
    if ((tid & 31) == 0)
        redv[tid >> 5] = make_float4(acc[0], acc[1], acc[2], acc[3]);
    __syncthreads();

    if (tid < BPB && (b0 + tid) < B) {
        float tot = 0.0f;
        #pragma unroll
        for (int w = 0; w < 8; ++w) {
            float4 r = redv[w];
            tot += (tid == 0) ? r.x : (tid == 1) ? r.y : (tid == 2) ? r.z : r.w;
        }
        const float DPHI = 6.2831853071795864769f / (float)NPH_K;
        float logC = s8[tid][6] + logf(tot * DPHI);
        out[b0 + tid] = logC - s8[tid][7];     // -logp
    }
}

// ---------------------------------------------------------------------------
// Inputs (metadata order): x[B,3], theta, phi, psi, kappa, beta, eta, alpha,
// rho (each [B], float32). Output: [B] float32.
// ---------------------------------------------------------------------------
extern "C" void kernel_launch(void* const* d_in, const int* in_sizes, int n_in,
                              void* d_out, int out_size)
{
    const float* x     = (const float*)d_in[0];
    const float* theta = (const float*)d_in[1];
    const float* phi   = (const float*)d_in[2];
    const float* psi   = (const float*)d_in[3];
    const float* kappa = (const float*)d_in[4];
    const float* beta  = (const float*)d_in[5];
    const float* eta   = (const float*)d_in[6];
    const float* alpha = (const float*)d_in[7];
    const float* rho   = (const float*)d_in[8];

    int B = in_sizes[1];   // theta element count
    if (B > MAXB) B = MAXB;

    fb8_init_kernel<<<1, 256>>>();
    int grid = (B + BPB - 1) / BPB;
    fb8_main_kernel<<<grid, 256>>>(x, theta, phi, psi, kappa, beta, eta,
                                   alpha, rho, (float*)d_out, B);
}